// round 13
// baseline (speedup 1.0000x reference)
#include <cuda_runtime.h>
#include <cuda_bf16.h>
#include <cuda_fp16.h>
#include <cstdint>

// Problem constants (fixed shapes)
#define TOK   100352          // B * H * W = 32 * 56 * 56
#define CIN   384
#define COUT  1152
#define NWIN  2048            // B * 64 windows
#define NHEAD 12

// Scratch
__device__ __half g_qkvh[(size_t)TOK * COUT];               // 231 MB (fp16)
__device__ __half g_Xh[(size_t)TOK * CIN];
__device__ __half g_Wh[(size_t)COUT * CIN];
__device__ int g_tokoff[64 * 49];
__device__ unsigned long long g_wmask[64 * 49];

// ---------------------------------------------------------------------------
// Kernel 0a: fp32 -> fp16
// ---------------------------------------------------------------------------
__global__ __launch_bounds__(256) void cvt_f16(const float* __restrict__ src,
                                               int n4, int which) {
    __half* dst = which ? g_Wh : g_Xh;
    int i = blockIdx.x * blockDim.x + threadIdx.x;
    if (i >= n4) return;
    float4 v = reinterpret_cast<const float4*>(src)[i];
    __half2 h0 = __floats2half2_rn(v.x, v.y);
    __half2 h1 = __floats2half2_rn(v.z, v.w);
    reinterpret_cast<__half2*>(dst)[2 * i]     = h0;
    reinterpret_cast<__half2*>(dst)[2 * i + 1] = h1;
}

// ---------------------------------------------------------------------------
// Kernel 0b: per-window-type token map + shift-mask tables (64 x 49)
// ---------------------------------------------------------------------------
__global__ void win_setup() {
    __shared__ int sreg[49];
    const int wi = blockIdx.x;
    const int n  = threadIdx.x;          // 0..48
    const int wh = wi >> 3, ww = wi & 7;
    const int r = n / 7, c = n - (n / 7) * 7;
    const int ys = wh * 7 + r;
    const int xs = ww * 7 + c;
    int y = ys + 3; if (y >= 56) y -= 56;
    int x = xs + 3; if (x >= 56) x -= 56;
    g_tokoff[wi * 49 + n] = y * 56 + x;
    const int rh = (ys < 49) ? 0 : ((ys < 53) ? 1 : 2);
    const int rw = (xs < 49) ? 0 : ((xs < 53) ? 1 : 2);
    sreg[n] = rh * 3 + rw;
    __syncthreads();
    unsigned long long bits = 0ull;
    const int ri = sreg[n];
    for (int m = 0; m < 49; m++)
        bits |= (unsigned long long)(sreg[m] != ri) << m;
    g_wmask[wi * 49 + n] = bits;
}

// attn swizzle: rows of 64B (32 fp16), chunk c (16B, 0..3) of row r.
__device__ __forceinline__ uint32_t tile_off(int r, int c) {
    return (uint32_t)((r >> 1) * 128 + ((((r & 1) * 4 + c) ^ ((r >> 1) & 7)) << 4));
}

#define LDSM4(R, addr) \
    asm volatile("ldmatrix.sync.aligned.m8n8.x4.shared.b16 {%0,%1,%2,%3}, [%4];" \
        : "=r"((R)[0]), "=r"((R)[1]), "=r"((R)[2]), "=r"((R)[3]) : "r"(addr))
#define LDSM2T(R, addr) \
    asm volatile("ldmatrix.sync.aligned.m8n8.x2.trans.shared.b16 {%0,%1}, [%2];" \
        : "=r"((R)[0]), "=r"((R)[1]) : "r"(addr))
#define MMA16816F16(C, A, B) \
    asm volatile("mma.sync.aligned.m16n8k16.row.col.f32.f16.f16.f32 " \
        "{%0,%1,%2,%3}, {%4,%5,%6,%7}, {%8,%9}, {%0,%1,%2,%3};" \
        : "+f"((C)[0]), "+f"((C)[1]), "+f"((C)[2]), "+f"((C)[3]) \
        : "r"((A)[0]), "r"((A)[1]), "r"((A)[2]), "r"((A)[3]), \
          "r"((B)[0]), "r"((B)[1]))
#define CPASYNC16(dst, src) \
    asm volatile("cp.async.cg.shared.global [%0], [%1], 16;" :: "r"(dst), "l"(src))

// ---------------------------------------------------------------------------
// Kernel 1: QKV GEMM (R10 best config: BK=32, 4-stage, x4-B ldmatrix)
// ---------------------------------------------------------------------------
#define GBM 128
#define GBN 128
#define GBK 32
#define STAGE_BYTES 16384
#define NIT 12
#define NPIPE 4
#define SMEM_TOTAL_G (NPIPE * STAGE_BYTES)

__global__ __launch_bounds__(256, 2) void qkv_gemm_mma(const float* __restrict__ bias) {
    extern __shared__ char sm_raw[];
    const uint32_t sbase = (uint32_t)__cvta_generic_to_shared(sm_raw);
    const int tid  = threadIdx.x;
    const int lane = tid & 31;
    const int warp = tid >> 5;
    const int n0 = blockIdx.x * GBN;
    const int m0 = blockIdx.y * GBM;
    const int wm = (warp >> 2) * 64;
    const int wn = (warp & 3) * 32;

    float acc[4][4][4];
    #pragma unroll
    for (int a = 0; a < 4; a++)
        #pragma unroll
        for (int b = 0; b < 4; b++)
            #pragma unroll
            for (int c = 0; c < 4; c++) acc[a][b][c] = 0.0f;

    auto load_stage = [&](int st) {
        const int k0 = st * GBK;
        uint32_t abase = sbase + (st % NPIPE) * STAGE_BYTES;
        uint32_t bbase = abase + 8192;
        #pragma unroll
        for (int u = 0; u < 2; u++) {
            int q = tid * 2 + u;
            int r = q >> 2, c = q & 3;
            uint32_t soff = tile_off(r, c);
            CPASYNC16(abase + soff, g_Xh + (size_t)(m0 + r) * CIN + k0 + c * 8);
            CPASYNC16(bbase + soff, g_Wh + (size_t)(n0 + r) * CIN + k0 + c * 8);
        }
        asm volatile("cp.async.commit_group;");
    };

    load_stage(0);
    load_stage(1);
    load_stage(2);

    #pragma unroll 1
    for (int it = 0; it < NIT; it++) {
        if (it + 3 < NIT) asm volatile("cp.async.wait_group 2;");
        else              asm volatile("cp.async.wait_group 0;");
        __syncthreads();
        if (it + 3 < NIT) load_stage(it + 3);

        uint32_t abase = sbase + (it % NPIPE) * STAGE_BYTES;
        uint32_t bbase = abase + 8192;

        #pragma unroll
        for (int kk = 0; kk < 2; kk++) {
            uint32_t Ah[4][4], Bh[2][4];
            int arow_in = lane & 15;
            int acol    = lane >> 4;
            #pragma unroll
            for (int mt = 0; mt < 4; mt++) {
                int row = wm + mt * 16 + arow_in;
                LDSM4(Ah[mt], abase + tile_off(row, kk * 2 + acol));
            }
            const int g = lane >> 3;
            #pragma unroll
            for (int np = 0; np < 2; np++) {
                int row = wn + (np * 2 + (g >> 1)) * 8 + (lane & 7);
                LDSM4(Bh[np], bbase + tile_off(row, kk * 2 + (g & 1)));
            }
            #pragma unroll
            for (int mt = 0; mt < 4; mt++)
                #pragma unroll
                for (int nt = 0; nt < 4; nt++)
                    MMA16816F16(acc[mt][nt], Ah[mt], &Bh[nt >> 1][(nt & 1) * 2]);
        }
    }

    #pragma unroll
    for (int mt = 0; mt < 4; mt++) {
        #pragma unroll
        for (int nt = 0; nt < 4; nt++) {
            int gm = m0 + wm + mt * 16 + (lane >> 2);
            int gn = n0 + wn + nt * 8 + (lane & 3) * 2;
            float b0 = __ldg(bias + gn);
            float b1 = __ldg(bias + gn + 1);
            __half2 h0 = __floats2half2_rn(acc[mt][nt][0] + b0, acc[mt][nt][1] + b1);
            __half2 h1 = __floats2half2_rn(acc[mt][nt][2] + b0, acc[mt][nt][3] + b1);
            *reinterpret_cast<__half2*>(&g_qkvh[(size_t)gm * COUT + gn]) = h0;
            *reinterpret_cast<__half2*>(&g_qkvh[(size_t)(gm + 8) * COUT + gn]) = h1;
        }
    }
}

// ---------------------------------------------------------------------------
// Kernel 2: tensor-core attention, LePE fused into O-fragment threads.
// ---------------------------------------------------------------------------
__global__ __launch_bounds__(128) void attn_kernel(const float* __restrict__ lepe_w,
                                                   const float* __restrict__ lepe_b,
                                                   float* __restrict__ out) {
    const int head = blockIdx.y;
    const int w    = blockIdx.x;
    const int b    = w >> 6;
    const int wi   = w & 63;

    __shared__ alignas(16) __half sQ[64 * 32];
    __shared__ alignas(16) __half sK[64 * 32];
    __shared__ alignas(16) __half sV[64 * 32];
    __shared__ alignas(16) float sO[49 * 36];
    __shared__ alignas(16) float swgt[9 * 32];
    __shared__ int stok[49];

    const int tid  = threadIdx.x;
    const int warp = tid >> 5;
    const int lane = tid & 31;

    if (tid < 49)
        stok[tid] = b * 3136 + __ldg(&g_tokoff[wi * 49 + tid]);
    for (int i = tid; i < 9 * 32; i += 128) {
        int tap = i >> 5, j = i & 31;
        swgt[i] = lepe_w[head * 288 + j * 9 + tap];
    }
    for (int i = tid; i < 180; i += 128) {
        int tens = i / 60, rem = i - tens * 60;
        int r = 49 + (rem >> 2), c = rem & 3;
        char* base = (tens == 0) ? (char*)sQ : (tens == 1) ? (char*)sK : (char*)sV;
        *reinterpret_cast<uint4*>(base + tile_off(r, c)) = make_uint4(0, 0, 0, 0);
    }
    __syncthreads();

    for (int i = tid; i < 196; i += 128) {
        int n = i >> 2, c = i & 3;
        const uint4* src = reinterpret_cast<const uint4*>(
            g_qkvh + (size_t)stok[n] * COUT + head * 32);
        *reinterpret_cast<uint4*>((char*)sQ + tile_off(n, c)) = src[c];
        *reinterpret_cast<uint4*>((char*)sK + tile_off(n, c)) = src[48 + c];
        *reinterpret_cast<uint4*>((char*)sV + tile_off(n, c)) = src[96 + c];
    }
    __syncthreads();

    const uint32_t qb = (uint32_t)__cvta_generic_to_shared(sQ);
    const uint32_t kb = (uint32_t)__cvta_generic_to_shared(sK);
    const uint32_t vb = (uint32_t)__cvta_generic_to_shared(sV);

    // ---- S = Q K^T ----
    const int i0 = warp * 16;
    float acc[8][4];
    #pragma unroll
    for (int nt = 0; nt < 8; nt++)
        #pragma unroll
        for (int c = 0; c < 4; c++) acc[nt][c] = 0.0f;

    #pragma unroll
    for (int kk = 0; kk < 2; kk++) {
        uint32_t A[4];
        LDSM4(A, qb + tile_off(i0 + (lane & 15), kk * 2 + (lane >> 4)));
        const int g = lane >> 3;
        #pragma unroll
        for (int np = 0; np < 4; np++) {
            uint32_t B[4];
            int row = (np * 2 + (g >> 1)) * 8 + (lane & 7);
            LDSM4(B, kb + tile_off(row, kk * 2 + (g & 1)));
            MMA16816F16(acc[np * 2],     A, &B[0]);
            MMA16816F16(acc[np * 2 + 1], A, &B[2]);
        }
    }

    // ---- scale + mask ----
    const float scale = 0.17677669529663687f;
    const int r0 = i0 + (lane >> 2);
    const int r1 = r0 + 8;
    const unsigned long long mb0 = __ldg(&g_wmask[wi * 49 + min(r0, 48)]);
    const unsigned long long mb1 = __ldg(&g_wmask[wi * 49 + min(r1, 48)]);
    #pragma unroll
    for (int nt = 0; nt < 8; nt++) {
        const int cb = nt * 8 + (lane & 3) * 2;
        float s0 = acc[nt][0] * scale;
        float s1 = acc[nt][1] * scale;
        float s2 = acc[nt][2] * scale;
        float s3 = acc[nt][3] * scale;
        if (cb >= 49)      s0 = -1e30f; else if ((mb0 >> cb) & 1)       s0 -= 100.0f;
        if (cb + 1 >= 49)  s1 = -1e30f; else if ((mb0 >> (cb + 1)) & 1) s1 -= 100.0f;
        if (cb >= 49)      s2 = -1e30f; else if ((mb1 >> cb) & 1)       s2 -= 100.0f;
        if (cb + 1 >= 49)  s3 = -1e30f; else if ((mb1 >> (cb + 1)) & 1) s3 -= 100.0f;
        acc[nt][0] = s0; acc[nt][1] = s1; acc[nt][2] = s2; acc[nt][3] = s3;
    }

    // ---- softmax ----
    float mx0 = -1e30f, mx1 = -1e30f;
    #pragma unroll
    for (int nt = 0; nt < 8; nt++) {
        mx0 = fmaxf(mx0, fmaxf(acc[nt][0], acc[nt][1]));
        mx1 = fmaxf(mx1, fmaxf(acc[nt][2], acc[nt][3]));
    }
    mx0 = fmaxf(mx0, __shfl_xor_sync(0xffffffff, mx0, 1));
    mx0 = fmaxf(mx0, __shfl_xor_sync(0xffffffff, mx0, 2));
    mx1 = fmaxf(mx1, __shfl_xor_sync(0xffffffff, mx1, 1));
    mx1 = fmaxf(mx1, __shfl_xor_sync(0xffffffff, mx1, 2));
    float sum0 = 0.0f, sum1 = 0.0f;
    #pragma unroll
    for (int nt = 0; nt < 8; nt++) {
        acc[nt][0] = __expf(acc[nt][0] - mx0); sum0 += acc[nt][0];
        acc[nt][1] = __expf(acc[nt][1] - mx0); sum0 += acc[nt][1];
        acc[nt][2] = __expf(acc[nt][2] - mx1); sum1 += acc[nt][2];
        acc[nt][3] = __expf(acc[nt][3] - mx1); sum1 += acc[nt][3];
    }
    sum0 += __shfl_xor_sync(0xffffffff, sum0, 1);
    sum0 += __shfl_xor_sync(0xffffffff, sum0, 2);
    sum1 += __shfl_xor_sync(0xffffffff, sum1, 1);
    sum1 += __shfl_xor_sync(0xffffffff, sum1, 2);
    const float inv0 = 1.0f / sum0;
    const float inv1 = 1.0f / sum1;

    // ---- pack P ----
    uint32_t Pa[4][4];
    #pragma unroll
    for (int k = 0; k < 4; k++) {
        __half2 h;
        h = __floats2half2_rn(acc[2 * k][0] * inv0, acc[2 * k][1] * inv0);
        Pa[k][0] = *reinterpret_cast<uint32_t*>(&h);
        h = __floats2half2_rn(acc[2 * k][2] * inv1, acc[2 * k][3] * inv1);
        Pa[k][1] = *reinterpret_cast<uint32_t*>(&h);
        h = __floats2half2_rn(acc[2 * k + 1][0] * inv0, acc[2 * k + 1][1] * inv0);
        Pa[k][2] = *reinterpret_cast<uint32_t*>(&h);
        h = __floats2half2_rn(acc[2 * k + 1][2] * inv1, acc[2 * k + 1][3] * inv1);
        Pa[k][3] = *reinterpret_cast<uint32_t*>(&h);
    }

    // ---- O = P V ----
    float oacc[4][4];
    #pragma unroll
    for (int nt = 0; nt < 4; nt++)
        #pragma unroll
        for (int c = 0; c < 4; c++) oacc[nt][c] = 0.0f;
    #pragma unroll
    for (int k = 0; k < 4; k++) {
        #pragma unroll
        for (int nt = 0; nt < 4; nt++) {
            uint32_t B[2];
            LDSM2T(B, vb + tile_off(k * 16 + (lane & 15), nt));
            MMA16816F16(oacc[nt], Pa[k], B);
        }
    }

    // ---- fused LePE: per thread, rows r0/r1, channels j=nt*8+(lane&3)*2 ----
    const int jbase = (lane & 3) * 2;
    float lep[2][8];
    #pragma unroll
    for (int rowi = 0; rowi < 2; rowi++) {
        const int n = rowi ? r1 : r0;
        #pragma unroll
        for (int nt = 0; nt < 4; nt++) {
            int j = nt * 8 + jbase;
            float2 bb = *reinterpret_cast<const float2*>(lepe_b + head * 32 + j);
            lep[rowi][nt * 2]     = bb.x;
            lep[rowi][nt * 2 + 1] = bb.y;
        }
        if (n < 49) {
            const int rr = n / 7, cc = n - (n / 7) * 7;
            #pragma unroll
            for (int dy = 0; dy < 3; dy++) {
                int y2 = rr + dy - 1;
                if ((unsigned)y2 >= 7u) continue;
                #pragma unroll
                for (int dx = 0; dx < 3; dx++) {
                    int x2 = cc + dx - 1;
                    if ((unsigned)x2 >= 7u) continue;
                    const int tap = dy * 3 + dx;
                    const int m = y2 * 7 + x2;
                    #pragma unroll
                    for (int nt = 0; nt < 4; nt++) {
                        int j = nt * 8 + jbase;
                        __half2 vh;
                        uint32_t addr = vb + tile_off(m, j >> 3) + (j & 7) * 2;
                        asm volatile("ld.shared.b32 %0, [%1];"
                                     : "=r"(*reinterpret_cast<uint32_t*>(&vh)) : "r"(addr));
                        float2 vf = __half22float2(vh);
                        float2 wg = *reinterpret_cast<const float2*>(&swgt[tap * 32 + j]);
                        lep[rowi][nt * 2]     = fmaf(vf.x, wg.x, lep[rowi][nt * 2]);
                        lep[rowi][nt * 2 + 1] = fmaf(vf.y, wg.y, lep[rowi][nt * 2 + 1]);
                    }
                }
            }
        }
    }

    // ---- stage O + LePE into sO ----
    #pragma unroll
    for (int nt = 0; nt < 4; nt++) {
        const int j = nt * 8 + jbase;
        if (r0 < 49)
            *reinterpret_cast<float2*>(&sO[r0 * 36 + j]) =
                make_float2(oacc[nt][0] + lep[0][nt * 2],
                            oacc[nt][1] + lep[0][nt * 2 + 1]);
        if (r1 < 49)
            *reinterpret_cast<float2*>(&sO[r1 * 36 + j]) =
                make_float2(oacc[nt][2] + lep[1][nt * 2],
                            oacc[nt][3] + lep[1][nt * 2 + 1]);
    }
    __syncthreads();

    // ---- row-coalesced scatter ----
    for (int i = tid; i < 49 * 8; i += 128) {
        int n = i >> 3, u = i & 7;
        reinterpret_cast<float4*>(out + (size_t)stok[n] * CIN + head * 32)[u] =
            reinterpret_cast<const float4*>(sO + n * 36)[u];
    }
}

// ---------------------------------------------------------------------------
extern "C" void kernel_launch(void* const* d_in, const int* in_sizes, int n_in,
                              void* d_out, int out_size) {
    const float* X    = (const float*)d_in[0];   // (32, 3136, 384)
    const float* Wqkv = (const float*)d_in[1];   // (1152, 384)
    const float* bqkv = (const float*)d_in[2];   // (1152,)
    const float* lw   = (const float*)d_in[3];   // (384,1,3,3)
    const float* lb   = (const float*)d_in[4];   // (384,)
    float* out = (float*)d_out;

    cudaFuncSetAttribute(qkv_gemm_mma,
                         cudaFuncAttributeMaxDynamicSharedMemorySize, SMEM_TOTAL_G);

    win_setup<<<64, 49>>>();
    cvt_f16<<<(TOK * CIN / 4) / 256, 256>>>(X, TOK * CIN / 4, 0);
    cvt_f16<<<(COUT * CIN / 4) / 256, 256>>>(Wqkv, COUT * CIN / 4, 1);
    qkv_gemm_mma<<<dim3(COUT / GBN, TOK / GBM), 256, SMEM_TOTAL_G>>>(bqkv);
    attn_kernel<<<dim3(NWIN, NHEAD), 128>>>(lw, lb, out);
}

// round 14
// speedup vs baseline: 1.5005x; 1.5005x over previous
#include <cuda_runtime.h>
#include <cuda_bf16.h>
#include <cuda_fp16.h>
#include <cstdint>

// Problem constants (fixed shapes)
#define TOK   100352          // B * H * W = 32 * 56 * 56
#define CIN   384
#define COUT  1152
#define NWIN  2048            // B * 64 windows
#define NHEAD 12

// Scratch
__device__ __half g_qkvh[(size_t)TOK * COUT];               // 231 MB (fp16)
__device__ __half g_Xh[(size_t)TOK * CIN];
__device__ __half g_Wh[(size_t)COUT * CIN];
__device__ int g_tokoff[64 * 49];
__device__ unsigned long long g_wmask[64 * 49];

#define NX4 (TOK * CIN / 4)
#define NW4 (COUT * CIN / 4)

// ---------------------------------------------------------------------------
// Kernel 0a: fp32 -> fp16 for BOTH X and W in one launch
// ---------------------------------------------------------------------------
__global__ __launch_bounds__(256) void cvt_f16(const float* __restrict__ X,
                                               const float* __restrict__ W) {
    int i = blockIdx.x * blockDim.x + threadIdx.x;
    const float* src;
    __half* dst;
    int idx;
    if (i < NX4) { src = X; dst = g_Xh; idx = i; }
    else if (i < NX4 + NW4) { src = W; dst = g_Wh; idx = i - NX4; }
    else return;
    float4 v = __ldg(reinterpret_cast<const float4*>(src) + idx);
    __half2 h0 = __floats2half2_rn(v.x, v.y);
    __half2 h1 = __floats2half2_rn(v.z, v.w);
    reinterpret_cast<__half2*>(dst)[2 * idx]     = h0;
    reinterpret_cast<__half2*>(dst)[2 * idx + 1] = h1;
}

// ---------------------------------------------------------------------------
// Kernel 0b: per-window-type token map + shift-mask tables (64 x 49)
// ---------------------------------------------------------------------------
__global__ void win_setup() {
    __shared__ int sreg[49];
    const int wi = blockIdx.x;
    const int n  = threadIdx.x;          // 0..48
    const int wh = wi >> 3, ww = wi & 7;
    const int r = n / 7, c = n - (n / 7) * 7;
    const int ys = wh * 7 + r;
    const int xs = ww * 7 + c;
    int y = ys + 3; if (y >= 56) y -= 56;
    int x = xs + 3; if (x >= 56) x -= 56;
    g_tokoff[wi * 49 + n] = y * 56 + x;
    const int rh = (ys < 49) ? 0 : ((ys < 53) ? 1 : 2);
    const int rw = (xs < 49) ? 0 : ((xs < 53) ? 1 : 2);
    sreg[n] = rh * 3 + rw;
    __syncthreads();
    unsigned long long bits = 0ull;
    const int ri = sreg[n];
    for (int m = 0; m < 49; m++)
        bits |= (unsigned long long)(sreg[m] != ri) << m;
    g_wmask[wi * 49 + n] = bits;
}

// attn swizzle: rows of 64B (32 fp16), chunk c (16B, 0..3) of row r.
__device__ __forceinline__ uint32_t tile_off(int r, int c) {
    return (uint32_t)((r >> 1) * 128 + ((((r & 1) * 4 + c) ^ ((r >> 1) & 7)) << 4));
}

#define LDSM4(R, addr) \
    asm volatile("ldmatrix.sync.aligned.m8n8.x4.shared.b16 {%0,%1,%2,%3}, [%4];" \
        : "=r"((R)[0]), "=r"((R)[1]), "=r"((R)[2]), "=r"((R)[3]) : "r"(addr))
#define LDSM2T(R, addr) \
    asm volatile("ldmatrix.sync.aligned.m8n8.x2.trans.shared.b16 {%0,%1}, [%2];" \
        : "=r"((R)[0]), "=r"((R)[1]) : "r"(addr))
#define MMA16816F16(C, A, B) \
    asm volatile("mma.sync.aligned.m16n8k16.row.col.f32.f16.f16.f32 " \
        "{%0,%1,%2,%3}, {%4,%5,%6,%7}, {%8,%9}, {%0,%1,%2,%3};" \
        : "+f"((C)[0]), "+f"((C)[1]), "+f"((C)[2]), "+f"((C)[3]) \
        : "r"((A)[0]), "r"((A)[1]), "r"((A)[2]), "r"((A)[3]), \
          "r"((B)[0]), "r"((B)[1]))
#define CPASYNC16(dst, src) \
    asm volatile("cp.async.cg.shared.global [%0], [%1], 16;" :: "r"(dst), "l"(src))

// ---------------------------------------------------------------------------
// Kernel 1: QKV GEMM (R10 best config: BK=32, 4-stage, x4-B ldmatrix)
// ---------------------------------------------------------------------------
#define GBM 128
#define GBN 128
#define GBK 32
#define STAGE_BYTES 16384
#define NIT 12
#define NPIPE 4
#define SMEM_TOTAL_G (NPIPE * STAGE_BYTES)

__global__ __launch_bounds__(256, 2) void qkv_gemm_mma(const float* __restrict__ bias) {
    extern __shared__ char sm_raw[];
    const uint32_t sbase = (uint32_t)__cvta_generic_to_shared(sm_raw);
    const int tid  = threadIdx.x;
    const int lane = tid & 31;
    const int warp = tid >> 5;
    const int n0 = blockIdx.x * GBN;
    const int m0 = blockIdx.y * GBM;
    const int wm = (warp >> 2) * 64;
    const int wn = (warp & 3) * 32;

    float acc[4][4][4];
    #pragma unroll
    for (int a = 0; a < 4; a++)
        #pragma unroll
        for (int b = 0; b < 4; b++)
            #pragma unroll
            for (int c = 0; c < 4; c++) acc[a][b][c] = 0.0f;

    auto load_stage = [&](int st) {
        const int k0 = st * GBK;
        uint32_t abase = sbase + (st % NPIPE) * STAGE_BYTES;
        uint32_t bbase = abase + 8192;
        #pragma unroll
        for (int u = 0; u < 2; u++) {
            int q = tid * 2 + u;
            int r = q >> 2, c = q & 3;
            uint32_t soff = tile_off(r, c);
            CPASYNC16(abase + soff, g_Xh + (size_t)(m0 + r) * CIN + k0 + c * 8);
            CPASYNC16(bbase + soff, g_Wh + (size_t)(n0 + r) * CIN + k0 + c * 8);
        }
        asm volatile("cp.async.commit_group;");
    };

    load_stage(0);
    load_stage(1);
    load_stage(2);

    #pragma unroll 1
    for (int it = 0; it < NIT; it++) {
        if (it + 3 < NIT) asm volatile("cp.async.wait_group 2;");
        else              asm volatile("cp.async.wait_group 0;");
        __syncthreads();
        if (it + 3 < NIT) load_stage(it + 3);

        uint32_t abase = sbase + (it % NPIPE) * STAGE_BYTES;
        uint32_t bbase = abase + 8192;

        #pragma unroll
        for (int kk = 0; kk < 2; kk++) {
            uint32_t Ah[4][4], Bh[2][4];
            int arow_in = lane & 15;
            int acol    = lane >> 4;
            #pragma unroll
            for (int mt = 0; mt < 4; mt++) {
                int row = wm + mt * 16 + arow_in;
                LDSM4(Ah[mt], abase + tile_off(row, kk * 2 + acol));
            }
            const int g = lane >> 3;
            #pragma unroll
            for (int np = 0; np < 2; np++) {
                int row = wn + (np * 2 + (g >> 1)) * 8 + (lane & 7);
                LDSM4(Bh[np], bbase + tile_off(row, kk * 2 + (g & 1)));
            }
            #pragma unroll
            for (int mt = 0; mt < 4; mt++)
                #pragma unroll
                for (int nt = 0; nt < 4; nt++)
                    MMA16816F16(acc[mt][nt], Ah[mt], &Bh[nt >> 1][(nt & 1) * 2]);
        }
    }

    #pragma unroll
    for (int mt = 0; mt < 4; mt++) {
        #pragma unroll
        for (int nt = 0; nt < 4; nt++) {
            int gm = m0 + wm + mt * 16 + (lane >> 2);
            int gn = n0 + wn + nt * 8 + (lane & 3) * 2;
            float b0 = __ldg(bias + gn);
            float b1 = __ldg(bias + gn + 1);
            __half2 h0 = __floats2half2_rn(acc[mt][nt][0] + b0, acc[mt][nt][1] + b1);
            __half2 h1 = __floats2half2_rn(acc[mt][nt][2] + b0, acc[mt][nt][3] + b1);
            *reinterpret_cast<__half2*>(&g_qkvh[(size_t)gm * COUT + gn]) = h0;
            *reinterpret_cast<__half2*>(&g_qkvh[(size_t)(gm + 8) * COUT + gn]) = h1;
        }
    }
}

// ---------------------------------------------------------------------------
// Kernel 2: tensor-core attention, LePE fused into O-fragment threads.
// ---------------------------------------------------------------------------
__global__ __launch_bounds__(128) void attn_kernel(const float* __restrict__ lepe_w,
                                                   const float* __restrict__ lepe_b,
                                                   float* __restrict__ out) {
    const int head = blockIdx.y;
    const int w    = blockIdx.x;
    const int b    = w >> 6;
    const int wi   = w & 63;

    __shared__ alignas(16) __half sQ[64 * 32];
    __shared__ alignas(16) __half sK[64 * 32];
    __shared__ alignas(16) __half sV[64 * 32];
    __shared__ alignas(16) float sO[49 * 36];
    __shared__ alignas(16) float swgt[9 * 32];
    __shared__ int stok[49];

    const int tid  = threadIdx.x;
    const int warp = tid >> 5;
    const int lane = tid & 31;

    if (tid < 49)
        stok[tid] = b * 3136 + __ldg(&g_tokoff[wi * 49 + tid]);
    for (int i = tid; i < 9 * 32; i += 128) {
        int tap = i >> 5, j = i & 31;
        swgt[i] = lepe_w[head * 288 + j * 9 + tap];
    }
    for (int i = tid; i < 180; i += 128) {
        int tens = i / 60, rem = i - tens * 60;
        int r = 49 + (rem >> 2), c = rem & 3;
        char* base = (tens == 0) ? (char*)sQ : (tens == 1) ? (char*)sK : (char*)sV;
        *reinterpret_cast<uint4*>(base + tile_off(r, c)) = make_uint4(0, 0, 0, 0);
    }
    __syncthreads();

    for (int i = tid; i < 196; i += 128) {
        int n = i >> 2, c = i & 3;
        const uint4* src = reinterpret_cast<const uint4*>(
            g_qkvh + (size_t)stok[n] * COUT + head * 32);
        *reinterpret_cast<uint4*>((char*)sQ + tile_off(n, c)) = src[c];
        *reinterpret_cast<uint4*>((char*)sK + tile_off(n, c)) = src[48 + c];
        *reinterpret_cast<uint4*>((char*)sV + tile_off(n, c)) = src[96 + c];
    }
    __syncthreads();

    const uint32_t qb = (uint32_t)__cvta_generic_to_shared(sQ);
    const uint32_t kb = (uint32_t)__cvta_generic_to_shared(sK);
    const uint32_t vb = (uint32_t)__cvta_generic_to_shared(sV);

    // ---- S = Q K^T ----
    const int i0 = warp * 16;
    float acc[8][4];
    #pragma unroll
    for (int nt = 0; nt < 8; nt++)
        #pragma unroll
        for (int c = 0; c < 4; c++) acc[nt][c] = 0.0f;

    #pragma unroll
    for (int kk = 0; kk < 2; kk++) {
        uint32_t A[4];
        LDSM4(A, qb + tile_off(i0 + (lane & 15), kk * 2 + (lane >> 4)));
        const int g = lane >> 3;
        #pragma unroll
        for (int np = 0; np < 4; np++) {
            uint32_t B[4];
            int row = (np * 2 + (g >> 1)) * 8 + (lane & 7);
            LDSM4(B, kb + tile_off(row, kk * 2 + (g & 1)));
            MMA16816F16(acc[np * 2],     A, &B[0]);
            MMA16816F16(acc[np * 2 + 1], A, &B[2]);
        }
    }

    // ---- scale + mask ----
    const float scale = 0.17677669529663687f;
    const int r0 = i0 + (lane >> 2);
    const int r1 = r0 + 8;
    const unsigned long long mb0 = __ldg(&g_wmask[wi * 49 + min(r0, 48)]);
    const unsigned long long mb1 = __ldg(&g_wmask[wi * 49 + min(r1, 48)]);
    #pragma unroll
    for (int nt = 0; nt < 8; nt++) {
        const int cb = nt * 8 + (lane & 3) * 2;
        float s0 = acc[nt][0] * scale;
        float s1 = acc[nt][1] * scale;
        float s2 = acc[nt][2] * scale;
        float s3 = acc[nt][3] * scale;
        if (cb >= 49)      s0 = -1e30f; else if ((mb0 >> cb) & 1)       s0 -= 100.0f;
        if (cb + 1 >= 49)  s1 = -1e30f; else if ((mb0 >> (cb + 1)) & 1) s1 -= 100.0f;
        if (cb >= 49)      s2 = -1e30f; else if ((mb1 >> cb) & 1)       s2 -= 100.0f;
        if (cb + 1 >= 49)  s3 = -1e30f; else if ((mb1 >> (cb + 1)) & 1) s3 -= 100.0f;
        acc[nt][0] = s0; acc[nt][1] = s1; acc[nt][2] = s2; acc[nt][3] = s3;
    }

    // ---- softmax ----
    float mx0 = -1e30f, mx1 = -1e30f;
    #pragma unroll
    for (int nt = 0; nt < 8; nt++) {
        mx0 = fmaxf(mx0, fmaxf(acc[nt][0], acc[nt][1]));
        mx1 = fmaxf(mx1, fmaxf(acc[nt][2], acc[nt][3]));
    }
    mx0 = fmaxf(mx0, __shfl_xor_sync(0xffffffff, mx0, 1));
    mx0 = fmaxf(mx0, __shfl_xor_sync(0xffffffff, mx0, 2));
    mx1 = fmaxf(mx1, __shfl_xor_sync(0xffffffff, mx1, 1));
    mx1 = fmaxf(mx1, __shfl_xor_sync(0xffffffff, mx1, 2));
    float sum0 = 0.0f, sum1 = 0.0f;
    #pragma unroll
    for (int nt = 0; nt < 8; nt++) {
        acc[nt][0] = __expf(acc[nt][0] - mx0); sum0 += acc[nt][0];
        acc[nt][1] = __expf(acc[nt][1] - mx0); sum0 += acc[nt][1];
        acc[nt][2] = __expf(acc[nt][2] - mx1); sum1 += acc[nt][2];
        acc[nt][3] = __expf(acc[nt][3] - mx1); sum1 += acc[nt][3];
    }
    sum0 += __shfl_xor_sync(0xffffffff, sum0, 1);
    sum0 += __shfl_xor_sync(0xffffffff, sum0, 2);
    sum1 += __shfl_xor_sync(0xffffffff, sum1, 1);
    sum1 += __shfl_xor_sync(0xffffffff, sum1, 2);
    const float inv0 = 1.0f / sum0;
    const float inv1 = 1.0f / sum1;

    // ---- pack P ----
    uint32_t Pa[4][4];
    #pragma unroll
    for (int k = 0; k < 4; k++) {
        __half2 h;
        h = __floats2half2_rn(acc[2 * k][0] * inv0, acc[2 * k][1] * inv0);
        Pa[k][0] = *reinterpret_cast<uint32_t*>(&h);
        h = __floats2half2_rn(acc[2 * k][2] * inv1, acc[2 * k][3] * inv1);
        Pa[k][1] = *reinterpret_cast<uint32_t*>(&h);
        h = __floats2half2_rn(acc[2 * k + 1][0] * inv0, acc[2 * k + 1][1] * inv0);
        Pa[k][2] = *reinterpret_cast<uint32_t*>(&h);
        h = __floats2half2_rn(acc[2 * k + 1][2] * inv1, acc[2 * k + 1][3] * inv1);
        Pa[k][3] = *reinterpret_cast<uint32_t*>(&h);
    }

    // ---- O = P V ----
    float oacc[4][4];
    #pragma unroll
    for (int nt = 0; nt < 4; nt++)
        #pragma unroll
        for (int c = 0; c < 4; c++) oacc[nt][c] = 0.0f;
    #pragma unroll
    for (int k = 0; k < 4; k++) {
        #pragma unroll
        for (int nt = 0; nt < 4; nt++) {
            uint32_t B[2];
            LDSM2T(B, vb + tile_off(k * 16 + (lane & 15), nt));
            MMA16816F16(oacc[nt], Pa[k], B);
        }
    }

    // ---- fused LePE: per thread, rows r0/r1, channels j=nt*8+(lane&3)*2 ----
    const int jbase = (lane & 3) * 2;
    float lep[2][8];
    #pragma unroll
    for (int rowi = 0; rowi < 2; rowi++) {
        const int n = rowi ? r1 : r0;
        #pragma unroll
        for (int nt = 0; nt < 4; nt++) {
            int j = nt * 8 + jbase;
            float2 bb = *reinterpret_cast<const float2*>(lepe_b + head * 32 + j);
            lep[rowi][nt * 2]     = bb.x;
            lep[rowi][nt * 2 + 1] = bb.y;
        }
        if (n < 49) {
            const int rr = n / 7, cc = n - (n / 7) * 7;
            #pragma unroll
            for (int dy = 0; dy < 3; dy++) {
                int y2 = rr + dy - 1;
                if ((unsigned)y2 >= 7u) continue;
                #pragma unroll
                for (int dx = 0; dx < 3; dx++) {
                    int x2 = cc + dx - 1;
                    if ((unsigned)x2 >= 7u) continue;
                    const int tap = dy * 3 + dx;
                    const int m = y2 * 7 + x2;
                    #pragma unroll
                    for (int nt = 0; nt < 4; nt++) {
                        int j = nt * 8 + jbase;
                        __half2 vh;
                        uint32_t addr = vb + tile_off(m, j >> 3) + (j & 7) * 2;
                        asm volatile("ld.shared.b32 %0, [%1];"
                                     : "=r"(*reinterpret_cast<uint32_t*>(&vh)) : "r"(addr));
                        float2 vf = __half22float2(vh);
                        float2 wg = *reinterpret_cast<const float2*>(&swgt[tap * 32 + j]);
                        lep[rowi][nt * 2]     = fmaf(vf.x, wg.x, lep[rowi][nt * 2]);
                        lep[rowi][nt * 2 + 1] = fmaf(vf.y, wg.y, lep[rowi][nt * 2 + 1]);
                    }
                }
            }
        }
    }

    // ---- stage O + LePE into sO ----
    #pragma unroll
    for (int nt = 0; nt < 4; nt++) {
        const int j = nt * 8 + jbase;
        if (r0 < 49)
            *reinterpret_cast<float2*>(&sO[r0 * 36 + j]) =
                make_float2(oacc[nt][0] + lep[0][nt * 2],
                            oacc[nt][1] + lep[0][nt * 2 + 1]);
        if (r1 < 49)
            *reinterpret_cast<float2*>(&sO[r1 * 36 + j]) =
                make_float2(oacc[nt][2] + lep[1][nt * 2],
                            oacc[nt][3] + lep[1][nt * 2 + 1]);
    }
    __syncthreads();

    // ---- row-coalesced scatter ----
    for (int i = tid; i < 49 * 8; i += 128) {
        int n = i >> 3, u = i & 7;
        reinterpret_cast<float4*>(out + (size_t)stok[n] * CIN + head * 32)[u] =
            reinterpret_cast<const float4*>(sO + n * 36)[u];
    }
}

// ---------------------------------------------------------------------------
extern "C" void kernel_launch(void* const* d_in, const int* in_sizes, int n_in,
                              void* d_out, int out_size) {
    const float* X    = (const float*)d_in[0];   // (32, 3136, 384)
    const float* Wqkv = (const float*)d_in[1];   // (1152, 384)
    const float* bqkv = (const float*)d_in[2];   // (1152,)
    const float* lw   = (const float*)d_in[3];   // (384,1,3,3)
    const float* lb   = (const float*)d_in[4];   // (384,)
    float* out = (float*)d_out;

    cudaFuncSetAttribute(qkv_gemm_mma,
                         cudaFuncAttributeMaxDynamicSharedMemorySize, SMEM_TOTAL_G);

    win_setup<<<64, 49>>>();
    cvt_f16<<<(NX4 + NW4 + 255) / 256, 256>>>(X, Wqkv);
    qkv_gemm_mma<<<dim3(COUT / GBN, TOK / GBM), 256, SMEM_TOTAL_G>>>(bqkv);
    attn_kernel<<<dim3(NWIN, NHEAD), 128>>>(lw, lb, out);
}